// round 15
// baseline (speedup 1.0000x reference)
#include <cuda_runtime.h>
#include <cuda_fp16.h>
#include <cstdint>

#define BB    4096
#define TT    80
#define HH    256
#define DIN   8
#define VV    80
#define G4H   1024
#define BH    (BB*HH)
#define OFF_H (BB*VV)
#define OFF_C (OFF_H + 2*BH)

// ---------------- device scratch (no allocation allowed) ----------------
__device__ __half g_W1[G4H*256];          // layer1 hh, packed cols, K contig
__device__ __half g_W2[G4H*512];          // layer2 [ih | hh]
__device__ float  g_bias1[VV*G4H];        // (W_ih0 @ emb[v]) packed col order
__device__ __half g_h1[2][BH], g_h2[2][BH];   // fp16 recurrent state (ping-pong)
__device__ float  g_h1f[BH], g_h2f[BH];       // fp32 shadow of FINAL h
__device__ float  g_c1[BH], g_c2[BH];

// packed column m -> original gate row (g*H + j); one thread's HMMA accum cols
// over an n8-tile-pair = gates i,f,g,o of one hidden unit j
__host__ __device__ __forceinline__ int orig_row(int m) {
    int j = 4 * (m >> 4) + ((m >> 1) & 3);
    int g = (m & 1) | (((m >> 3) & 1) << 1);
    return g * HH + j;
}

// ---------------- PTX helpers ----------------
__device__ __forceinline__ uint32_t smem_u32(const void* p) {
    uint32_t a;
    asm("{ .reg .u64 t; cvta.to.shared.u64 t, %1; cvt.u32.u64 %0, t; }" : "=r"(a) : "l"(p));
    return a;
}
__device__ __forceinline__ void cpa16(uint32_t s, const void* g) {
    asm volatile("cp.async.cg.shared.global [%0], [%1], 16;" :: "r"(s), "l"(g));
}
__device__ __forceinline__ void cpa_commit() {
    asm volatile("cp.async.commit_group;" ::: "memory");
}
template<int N>
__device__ __forceinline__ void cpa_wait() {
    asm volatile("cp.async.wait_group %0;" :: "n"(N) : "memory");
}
__device__ __forceinline__ void ldsm4(uint32_t* r, uint32_t addr) {
    asm volatile("ldmatrix.sync.aligned.m8n8.x4.shared.b16 {%0,%1,%2,%3}, [%4];"
                 : "=r"(r[0]), "=r"(r[1]), "=r"(r[2]), "=r"(r[3]) : "r"(addr));
}
__device__ __forceinline__ void mma16816h(float* c, const uint32_t* a, uint32_t b0, uint32_t b1) {
    asm volatile(
        "mma.sync.aligned.m16n8k16.row.col.f32.f16.f16.f32 "
        "{%0,%1,%2,%3}, {%4,%5,%6,%7}, {%8,%9}, {%0,%1,%2,%3};"
        : "+f"(c[0]), "+f"(c[1]), "+f"(c[2]), "+f"(c[3])
        : "r"(a[0]), "r"(a[1]), "r"(a[2]), "r"(a[3]), "r"(b0), "r"(b1));
}

__device__ __forceinline__ float sigf(float x)  { return 1.0f / (1.0f + __expf(-x)); }
__device__ __forceinline__ float tanhp(float x) { return 2.0f * sigf(2.0f * x) - 1.0f; }

// SMEM stage: A 8K (64 rows x 128B) | B 8K (64 rows x 128B), SW128, 2 stages
// c-state prefetch (64 rows x 16 fp32, stride 80B) reuses stage 0
#define STG   16384
#define AOFF  0
#define BOFF  8192
#define SMEM_TOTAL (2*STG)
#define CROWB 80

// =========================================================================
// Fused HMMA LSTM step, both layers in one launch.
//   which==1 (layer1 @ t1): K=256 (nc=4), A = h1[p1]
//   which==0 (layer2 @ t2): K=512 (nc=8), A = [h1_cur | h2_prev]
// CTA tile: M=64 x N=64 packed cols (16 hidden units). 4 warps (2M x 2N) of 32x32.
// launch_bounds(128,4): 128-reg budget -> ptxas double-buffers fragments
// across ks iterations (R12->R14 showed regs beat warp count here).
// mode: 0 = z0->layer2(t2), z1->layer1(t1); 1 = layer1 only; 2 = layer2 only
// =========================================================================
__global__ void __launch_bounds__(128, 4) lstm_step(const int* __restrict__ x,
                                                    int t2, int t1, int mode)
{
    extern __shared__ char sm[];
    const uint32_t smb = smem_u32(sm);
    const int tid  = threadIdx.x;
    const int lane = tid & 31, wid = tid >> 5;
    const int wm = wid & 1, wn = wid >> 1;
    const int bx = blockIdx.x;             // 0..15 n-tiles (64 packed cols each)
    const int by = blockIdx.y;             // 0..63 m-tiles (64 rows each)
    const int mbase = by * 64, nb = bx * 64, jbase = bx * 16;

    const int which = (mode == 0) ? (int)blockIdx.z : (mode == 2 ? 0 : 1);

    int nc, KW, tt;
    const __half *W, *A0, *A1;
    __half* Oh;
    float *Of, *cst;
    if (which == 1) {                       // layer 1 at time t1
        const int p = t1 & 1;
        nc = 4; KW = 256; tt = t1;
        W = g_W1;
        A0 = g_h1[p]; A1 = A0;
        Oh = g_h1[p ^ 1]; Of = g_h1f; cst = g_c1;
    } else {                                // layer 2 at time t2
        const int p = t2 & 1;
        nc = 8; KW = 512; tt = t2;
        W = g_W2;
        A0 = g_h1[p ^ 1];                   // h1 at current t2
        A1 = g_h2[p];                       // h2 at t2-1
        Oh = g_h2[p ^ 1]; Of = g_h2f; cst = g_c2;
    }
    const bool wf = (tt == TT - 1);

    // prefetch layer-1 token indices early (latency hides under mainloop)
    const int r = lane >> 2, q = lane & 3;
    int v0 = 0, v1 = 0, v2 = 0, v3 = 0;
    if (which == 1) {
        const int ba = mbase + wm * 32 + r;
        v0 = x[ba * TT + tt];         v1 = x[(ba + 8) * TT + tt];
        v2 = x[(ba + 16) * TT + tt];  v3 = x[(ba + 24) * TT + tt];
    }

    float acc[2][4][4];
    #pragma unroll
    for (int i = 0; i < 2; i++)
        #pragma unroll
        for (int j = 0; j < 4; j++)
            #pragma unroll
            for (int k = 0; k < 4; k++) acc[i][j][k] = 0.f;

    // per-thread cp.async offsets: 128 threads cover 16 rows x 8 chunks per iter
    const int lrow = tid >> 3, lch = tid & 7;
    const uint32_t lso = (uint32_t)((lrow * 128 + lch * 16) ^ ((lrow & 7) << 4));

    // ---- hoisted ldsm bases (unswizzled) + XOR masks ----
    // addr = (X + stage + ks*32) ^ mask.  base bits 5:6 are zero (only bit 4
    // from the 16B-half select), so + ks*32 never carries into mask bits 4:6.
    uint32_t Xa[2], xva[2], Xb[2], xvb[2];
    #pragma unroll
    for (int mt = 0; mt < 2; ++mt) {
        const int row = wm * 32 + mt * 16 + (lane & 15);
        Xa[mt]  = smb + AOFF + (uint32_t)(row * 128 + ((lane >> 4) & 1) * 16);
        xva[mt] = (uint32_t)((row & 7) << 4);
    }
    #pragma unroll
    for (int np = 0; np < 2; ++np) {
        const int brow = wn * 32 + np * 16 + (lane & 7) + ((lane >> 4) & 1) * 8;
        Xb[np]  = smb + BOFF + (uint32_t)(brow * 128 + ((lane >> 3) & 1) * 16);
        xvb[np] = (uint32_t)((brow & 7) << 4);
    }

    auto load_chunk = [&](int c) {
        const uint32_t sb = smb + (c & 1) * STG;
        const __half* ap = (c < 4) ? A0 : A1;
        const int ko = (c & 3) * 64;
        #pragma unroll
        for (int it = 0; it < 4; ++it) {                 // A: 64 rows x 8 16B-chunks
            const int row = lrow + it * 16;
            const uint32_t so = lso + it * 16 * 128;
            cpa16(sb + AOFF + so, ap + (mbase + row) * HH + ko + lch * 8);
        }
        #pragma unroll
        for (int it = 0; it < 4; ++it) {                 // B: 64 rows x 8 chunks
            const int row = lrow + it * 16;
            const uint32_t so = lso + it * 16 * 128;
            cpa16(sb + BOFF + so, W + (nb + row) * KW + c * 64 + lch * 8);
        }
        cpa_commit();
    };

    // c-state prefetch into stage 0 (free during last chunk's compute)
    const int crow = tid >> 2, cch = tid & 3;
    auto load_cstate = [&]() {
        #pragma unroll
        for (int it = 0; it < 2; ++it) {
            const int row = crow + it * 32;
            cpa16(smb + (uint32_t)(row * CROWB + cch * 16),
                  cst + (size_t)(mbase + row) * HH + jbase + cch * 4);
        }
        cpa_commit();
    };

    // --- single-sync 2-stage pipeline: wait; sync; issue next load; compute ---
    load_chunk(0);
    for (int c = 0; c < nc; ++c) {
        cpa_wait<0>();
        __syncthreads();            // separates compute(c-1) readers from load(c+1) writers
        if (c + 1 < nc) load_chunk(c + 1);
        else            load_cstate();

        const uint32_t stg = (uint32_t)(c & 1) * STG;
        #pragma unroll
        for (int ks = 0; ks < 4; ++ks) {
            // batch the 4 fragment loads of this ks, then stream 8 MMAs;
            // with the 128-reg budget ptxas pipelines ks+1 loads under these MMAs
            uint32_t af[2][4], bf[2][4];
            #pragma unroll
            for (int mt = 0; mt < 2; ++mt)
                ldsm4(af[mt], (Xa[mt] + stg + (uint32_t)(ks * 32)) ^ xva[mt]);
            #pragma unroll
            for (int np = 0; np < 2; ++np)
                ldsm4(bf[np], (Xb[np] + stg + (uint32_t)(ks * 32)) ^ xvb[np]);
            #pragma unroll
            for (int np = 0; np < 2; ++np)
                #pragma unroll
                for (int mt = 0; mt < 2; ++mt)
                    #pragma unroll
                    for (int h = 0; h < 2; ++h)
                        mma16816h(acc[mt][2*np + h], af[mt], bf[np][2*h], bf[np][2*h + 1]);
        }
    }
    cpa_wait<0>();
    __syncthreads();                // c-state visible to all epilogue readers

    // ---- fused LSTM epilogue: all 4 gates of (b, j) live in this thread ----
    #pragma unroll
    for (int mt = 0; mt < 2; ++mt) {
        const int srow = wm * 32 + mt * 16 + r;
        const int b0 = mbase + srow;
        const int w0 = (mt == 0) ? v0 : v2;
        const int w1 = (mt == 0) ? v1 : v3;
        #pragma unroll
        for (int np = 0; np < 2; ++np) {
            const int jl = wn * 8 + np * 4 + q;
            const int j = jbase + jl;
            float gi0 = acc[mt][2*np][0],   gf0 = acc[mt][2*np][1];
            float gi1 = acc[mt][2*np][2],   gf1 = acc[mt][2*np][3];
            float gg0 = acc[mt][2*np+1][0], go0 = acc[mt][2*np+1][1];
            float gg1 = acc[mt][2*np+1][2], go1 = acc[mt][2*np+1][3];
            if (which == 1) {
                const int m0 = bx * 64 + wn * 32 + np * 16 + 2 * q;
                float2 u;
                u = *(const float2*)(g_bias1 + w0 * G4H + m0);     gi0 += u.x; gf0 += u.y;
                u = *(const float2*)(g_bias1 + w0 * G4H + m0 + 8); gg0 += u.x; go0 += u.y;
                u = *(const float2*)(g_bias1 + w1 * G4H + m0);     gi1 += u.x; gf1 += u.y;
                u = *(const float2*)(g_bias1 + w1 * G4H + m0 + 8); gg1 += u.x; go1 += u.y;
            }
            {
                const int idx = b0 * HH + j;
                float co = *(const float*)(sm + srow * CROWB + jl * 4);
                float cn = sigf(gf0) * co + sigf(gi0) * tanhp(gg0);
                cst[idx] = cn;
                float hn = sigf(go0) * tanhp(cn);
                Oh[idx] = __float2half(hn);
                if (wf) Of[idx] = hn;
            }
            {
                const int idx = (b0 + 8) * HH + j;
                float co = *(const float*)(sm + (srow + 8) * CROWB + jl * 4);
                float cn = sigf(gf1) * co + sigf(gi1) * tanhp(gg1);
                cst[idx] = cn;
                float hn = sigf(go1) * tanhp(cn);
                Oh[idx] = __float2half(hn);
                if (wf) Of[idx] = hn;
            }
        }
    }
}

// =========================================================================
// ONE merged prologue kernel (packing + init)
// =========================================================================
#define S_W1   (G4H*256)
#define S_W2   (G4H*512)
#define S_B1   (VV*G4H)
#define S_IN   BH
#define S_TOT  (S_W1 + S_W2 + S_B1 + S_IN)

__global__ void prologue(const float* __restrict__ h0,  const float* __restrict__ c0,
                         const float* __restrict__ emb, const float* __restrict__ Wih0,
                         const float* __restrict__ Whh0,const float* __restrict__ Wih1,
                         const float* __restrict__ Whh1)
{
    int idx = blockIdx.x * 256 + threadIdx.x;
    if (idx < S_W1) {
        int m = idx >> 8, k = idx & 255;
        g_W1[idx] = __float2half(Whh0[orig_row(m) * HH + k]);
        return;
    }
    idx -= S_W1;
    if (idx < S_W2) {
        int m = idx >> 9, k = idx & 511;
        int row = orig_row(m);
        g_W2[idx] = __float2half((k < HH) ? Wih1[row * HH + k] : Whh1[row * HH + k - HH]);
        return;
    }
    idx -= S_W2;
    if (idx < S_B1) {
        int v = idx >> 10, m = idx & 1023;
        int row = orig_row(m);
        float s = 0.f;
        #pragma unroll
        for (int d = 0; d < DIN; ++d) s += emb[v * DIN + d] * Wih0[row * DIN + d];
        g_bias1[idx] = s;
        return;
    }
    idx -= S_B1;
    if (idx < S_IN) {
        float a = h0[idx], b = h0[BH + idx];
        g_h1[0][idx] = __float2half(a);  g_h1f[idx] = a;
        g_h2[0][idx] = __float2half(b);  g_h2f[idx] = b;
        g_c1[idx] = c0[idx];
        g_c2[idx] = c0[BH + idx];
    }
}

__global__ void fc_kernel(const float* __restrict__ Wf, const float* __restrict__ bf,
                          float* __restrict__ out)
{
    __shared__ float hs[8][HH];
    const int b0 = blockIdx.x * 8;
    for (int i = threadIdx.x; i < 8 * HH; i += 256)
        hs[i / HH][i % HH] = g_h2f[(b0 + i / HH) * HH + (i % HH)];
    __syncthreads();
    for (int idx = threadIdx.x; idx < 8 * VV; idx += 256) {
        const int bl = idx / VV, v = idx % VV;
        const float* __restrict__ wr = Wf + v * HH;
        const float* __restrict__ hp = hs[bl];
        float s = bf[v];
        #pragma unroll 8
        for (int k = 0; k < HH; k++) s += hp[k] * wr[k];
        out[(b0 + bl) * VV + v] = s;
    }
}
__global__ void finalize(float* __restrict__ out) {
    int i = blockIdx.x * 256 + threadIdx.x;
    if (i < BH) {
        out[OFF_H + i]      = g_h1f[i];
        out[OFF_H + BH + i] = g_h2f[i];
        out[OFF_C + i]      = g_c1[i];
        out[OFF_C + BH + i] = g_c2[i];
    }
}

// =========================================================================
extern "C" void kernel_launch(void* const* d_in, const int* in_sizes, int n_in,
                              void* d_out, int out_size)
{
    const int*   x    = (const int*)  d_in[0];
    const float* h0   = (const float*)d_in[1];
    const float* c0   = (const float*)d_in[2];
    const float* emb  = (const float*)d_in[3];
    const float* Wih0 = (const float*)d_in[4];
    const float* Whh0 = (const float*)d_in[5];
    const float* Wih1 = (const float*)d_in[6];
    const float* Whh1 = (const float*)d_in[7];
    const float* fcW  = (const float*)d_in[8];
    const float* fcb  = (const float*)d_in[9];
    float* out = (float*)d_out;

    cudaFuncSetAttribute(lstm_step, cudaFuncAttributeMaxDynamicSharedMemorySize, SMEM_TOTAL);

    prologue<<<(S_TOT + 255) / 256, 256>>>(h0, c0, emb, Wih0, Whh0, Wih1, Whh1);

    // layer1(0); then fused {layer2(t), layer1(t+1)} for t=0..78; then layer2(79)
    lstm_step<<<dim3(16, 64, 1), 128, SMEM_TOTAL>>>(x, 0, 0, 1);
    for (int t = 0; t < TT - 1; ++t)
        lstm_step<<<dim3(16, 64, 2), 128, SMEM_TOTAL>>>(x, t, t + 1, 0);
    lstm_step<<<dim3(16, 64, 1), 128, SMEM_TOTAL>>>(x, TT - 1, 0, 2);

    fc_kernel<<<BB / 8, 256>>>(fcW, fcb, out);
    finalize <<<(BH + 255) / 256, 256>>>(out);
}

// round 16
// speedup vs baseline: 1.1881x; 1.1881x over previous
#include <cuda_runtime.h>
#include <cuda_fp16.h>
#include <cstdint>

#define BB    4096
#define TT    80
#define HH    256
#define DIN   8
#define VV    80
#define G4H   1024
#define BH    (BB*HH)
#define OFF_H (BB*VV)
#define OFF_C (OFF_H + 2*BH)

// ---------------- device scratch (no allocation allowed) ----------------
__device__ __half g_W1[G4H*256];          // layer1 hh, packed cols, K contig
__device__ __half g_W2[G4H*512];          // layer2 [ih | hh]
__device__ float  g_bias1[VV*G4H];        // (W_ih0 @ emb[v]) packed col order
__device__ __half g_h1[2][BH], g_h2[2][BH];   // fp16 recurrent state (ping-pong)
__device__ float  g_h1f[BH], g_h2f[BH];       // fp32 shadow of FINAL h
__device__ float  g_c1[BH], g_c2[BH];

// packed column m -> original gate row (g*H + j); one thread's HMMA accum cols
// over an n8-tile-pair = gates i,f,g,o of one hidden unit j
__host__ __device__ __forceinline__ int orig_row(int m) {
    int j = 4 * (m >> 4) + ((m >> 1) & 3);
    int g = (m & 1) | (((m >> 3) & 1) << 1);
    return g * HH + j;
}

// ---------------- PTX helpers ----------------
__device__ __forceinline__ uint32_t smem_u32(const void* p) {
    uint32_t a;
    asm("{ .reg .u64 t; cvta.to.shared.u64 t, %1; cvt.u32.u64 %0, t; }" : "=r"(a) : "l"(p));
    return a;
}
__device__ __forceinline__ void cpa16(uint32_t s, const void* g) {
    asm volatile("cp.async.cg.shared.global [%0], [%1], 16;" :: "r"(s), "l"(g));
}
__device__ __forceinline__ void cpa_commit() {
    asm volatile("cp.async.commit_group;" ::: "memory");
}
template<int N>
__device__ __forceinline__ void cpa_wait() {
    asm volatile("cp.async.wait_group %0;" :: "n"(N) : "memory");
}
__device__ __forceinline__ void ldsm4(uint32_t* r, uint32_t addr) {
    asm volatile("ldmatrix.sync.aligned.m8n8.x4.shared.b16 {%0,%1,%2,%3}, [%4];"
                 : "=r"(r[0]), "=r"(r[1]), "=r"(r[2]), "=r"(r[3]) : "r"(addr));
}
__device__ __forceinline__ void mma16816h(float* c, const uint32_t* a, uint32_t b0, uint32_t b1) {
    asm volatile(
        "mma.sync.aligned.m16n8k16.row.col.f32.f16.f16.f32 "
        "{%0,%1,%2,%3}, {%4,%5,%6,%7}, {%8,%9}, {%0,%1,%2,%3};"
        : "+f"(c[0]), "+f"(c[1]), "+f"(c[2]), "+f"(c[3])
        : "r"(a[0]), "r"(a[1]), "r"(a[2]), "r"(a[3]), "r"(b0), "r"(b1));
}

// HW tanh (sm_75+): 1 MUFU op, abs err ~1e-5
__device__ __forceinline__ float tanhap(float x) {
    float y;
    asm("tanh.approx.f32 %0, %1;" : "=f"(y) : "f"(x));
    return y;
}
__device__ __forceinline__ float sigf(float x) {
    return fmaf(0.5f, tanhap(0.5f * x), 0.5f);
}

// SMEM stage: A 8K (64 rows x 128B) | B 8K (64 rows x 128B), SW128, 2 stages
// c-state prefetch (64 rows x 16 fp32, stride 80B) reuses stage 0
#define STG   16384
#define AOFF  0
#define BOFF  8192
#define SMEM_TOTAL (2*STG)
#define CROWB 80

// =========================================================================
// Fused HMMA LSTM step, both layers in one launch.
//   which==1 (layer1 @ t1): K=256 (nc=4), A = h1[p1]
//   which==0 (layer2 @ t2): K=512 (nc=8), A = [h1_cur | h2_prev]
// CTA tile: M=64 x N=64 packed cols (16 hidden units). 4 warps (2M x 2N) of 32x32.
// launch_bounds(128,5): reg budget ~102; per-ks batched fragment loads.
// mode: 0 = z0->layer2(t2), z1->layer1(t1); 1 = layer1 only; 2 = layer2 only
// =========================================================================
__global__ void __launch_bounds__(128, 5) lstm_step(const int* __restrict__ x,
                                                    int t2, int t1, int mode)
{
    extern __shared__ char sm[];
    const uint32_t smb = smem_u32(sm);
    const int tid  = threadIdx.x;
    const int lane = tid & 31, wid = tid >> 5;
    const int wm = wid & 1, wn = wid >> 1;
    const int bx = blockIdx.x;             // 0..15 n-tiles (64 packed cols each)
    const int by = blockIdx.y;             // 0..63 m-tiles (64 rows each)
    const int mbase = by * 64, nb = bx * 64, jbase = bx * 16;

    const int which = (mode == 0) ? (int)blockIdx.z : (mode == 2 ? 0 : 1);

    int nc, KW, tt;
    const __half *W, *A0, *A1;
    __half* Oh;
    float *Of, *cst;
    if (which == 1) {                       // layer 1 at time t1
        const int p = t1 & 1;
        nc = 4; KW = 256; tt = t1;
        W = g_W1;
        A0 = g_h1[p]; A1 = A0;
        Oh = g_h1[p ^ 1]; Of = g_h1f; cst = g_c1;
    } else {                                // layer 2 at time t2
        const int p = t2 & 1;
        nc = 8; KW = 512; tt = t2;
        W = g_W2;
        A0 = g_h1[p ^ 1];                   // h1 at current t2
        A1 = g_h2[p];                       // h2 at t2-1
        Oh = g_h2[p ^ 1]; Of = g_h2f; cst = g_c2;
    }
    const bool wf = (tt == TT - 1);

    // prefetch layer-1 token indices early (latency hides under mainloop)
    const int r = lane >> 2, q = lane & 3;
    int v0 = 0, v1 = 0, v2 = 0, v3 = 0;
    if (which == 1) {
        const int ba = mbase + wm * 32 + r;
        v0 = x[ba * TT + tt];         v1 = x[(ba + 8) * TT + tt];
        v2 = x[(ba + 16) * TT + tt];  v3 = x[(ba + 24) * TT + tt];
    }

    float acc[2][4][4];
    #pragma unroll
    for (int i = 0; i < 2; i++)
        #pragma unroll
        for (int j = 0; j < 4; j++)
            #pragma unroll
            for (int k = 0; k < 4; k++) acc[i][j][k] = 0.f;

    // per-thread cp.async offsets: 128 threads cover 16 rows x 8 chunks per iter
    const int lrow = tid >> 3, lch = tid & 7;
    const uint32_t lso = (uint32_t)((lrow * 128 + lch * 16) ^ ((lrow & 7) << 4));

    auto load_chunk = [&](int c) {
        const uint32_t sb = smb + (c & 1) * STG;
        const __half* ap = (c < 4) ? A0 : A1;
        const int ko = (c & 3) * 64;
        #pragma unroll
        for (int it = 0; it < 4; ++it) {                 // A: 64 rows x 8 16B-chunks
            const int row = lrow + it * 16;
            const uint32_t so = lso + it * 16 * 128;
            cpa16(sb + AOFF + so, ap + (mbase + row) * HH + ko + lch * 8);
        }
        #pragma unroll
        for (int it = 0; it < 4; ++it) {                 // B: 64 rows x 8 chunks
            const int row = lrow + it * 16;
            const uint32_t so = lso + it * 16 * 128;
            cpa16(sb + BOFF + so, W + (nb + row) * KW + c * 64 + lch * 8);
        }
        cpa_commit();
    };

    // c-state prefetch into stage 0 (free during last chunk's compute)
    const int crow = tid >> 2, cch = tid & 3;
    auto load_cstate = [&]() {
        #pragma unroll
        for (int it = 0; it < 2; ++it) {
            const int row = crow + it * 32;
            cpa16(smb + (uint32_t)(row * CROWB + cch * 16),
                  cst + (size_t)(mbase + row) * HH + jbase + cch * 4);
        }
        cpa_commit();
    };

    // --- single-sync 2-stage pipeline: wait; sync; issue next load; compute ---
    load_chunk(0);
    for (int c = 0; c < nc; ++c) {
        cpa_wait<0>();
        __syncthreads();            // separates compute(c-1) readers from load(c+1) writers
        if (c + 1 < nc) load_chunk(c + 1);
        else            load_cstate();

        const uint32_t sb = smb + (c & 1) * STG;
        #pragma unroll
        for (int ks = 0; ks < 4; ++ks) {
            // batch the 4 fragment loads of this ks, then stream 8 MMAs;
            // next ks's ldsm issue behind these MMAs (WAR clears at operand read)
            uint32_t af[2][4], bf[2][4];
            #pragma unroll
            for (int mt = 0; mt < 2; ++mt) {
                const int row  = wm * 32 + mt * 16 + (lane & 15);
                const uint32_t so = (uint32_t)((row * 128 + ks * 32 + ((lane >> 4) & 1) * 16)
                                               ^ ((row & 7) << 4));
                ldsm4(af[mt], sb + AOFF + so);
            }
            #pragma unroll
            for (int np = 0; np < 2; ++np) {
                const int brow = wn * 32 + np * 16 + (lane & 7) + ((lane >> 4) & 1) * 8;
                const uint32_t so = (uint32_t)((brow * 128 + ks * 32 + ((lane >> 3) & 1) * 16)
                                               ^ ((brow & 7) << 4));
                ldsm4(bf[np], sb + BOFF + so);
            }
            #pragma unroll
            for (int np = 0; np < 2; ++np)
                #pragma unroll
                for (int mt = 0; mt < 2; ++mt)
                    #pragma unroll
                    for (int h = 0; h < 2; ++h)
                        mma16816h(acc[mt][2*np + h], af[mt], bf[np][2*h], bf[np][2*h + 1]);
        }
    }
    cpa_wait<0>();
    __syncthreads();                // c-state visible to all epilogue readers

    // ---- fused LSTM epilogue: all 4 gates of (b, j) live in this thread ----
    #pragma unroll
    for (int mt = 0; mt < 2; ++mt) {
        const int srow = wm * 32 + mt * 16 + r;
        const int b0 = mbase + srow;
        const int w0 = (mt == 0) ? v0 : v2;
        const int w1 = (mt == 0) ? v1 : v3;
        #pragma unroll
        for (int np = 0; np < 2; ++np) {
            const int jl = wn * 8 + np * 4 + q;
            const int j = jbase + jl;
            float gi0 = acc[mt][2*np][0],   gf0 = acc[mt][2*np][1];
            float gi1 = acc[mt][2*np][2],   gf1 = acc[mt][2*np][3];
            float gg0 = acc[mt][2*np+1][0], go0 = acc[mt][2*np+1][1];
            float gg1 = acc[mt][2*np+1][2], go1 = acc[mt][2*np+1][3];
            if (which == 1) {
                const int m0 = bx * 64 + wn * 32 + np * 16 + 2 * q;
                float2 u;
                u = *(const float2*)(g_bias1 + w0 * G4H + m0);     gi0 += u.x; gf0 += u.y;
                u = *(const float2*)(g_bias1 + w0 * G4H + m0 + 8); gg0 += u.x; go0 += u.y;
                u = *(const float2*)(g_bias1 + w1 * G4H + m0);     gi1 += u.x; gf1 += u.y;
                u = *(const float2*)(g_bias1 + w1 * G4H + m0 + 8); gg1 += u.x; go1 += u.y;
            }
            {
                const int idx = b0 * HH + j;
                float co = *(const float*)(sm + srow * CROWB + jl * 4);
                float cn = sigf(gf0) * co + sigf(gi0) * tanhap(gg0);
                cst[idx] = cn;
                float hn = sigf(go0) * tanhap(cn);
                Oh[idx] = __float2half(hn);
                if (wf) Of[idx] = hn;
            }
            {
                const int idx = (b0 + 8) * HH + j;
                float co = *(const float*)(sm + (srow + 8) * CROWB + jl * 4);
                float cn = sigf(gf1) * co + sigf(gi1) * tanhap(gg1);
                cst[idx] = cn;
                float hn = sigf(go1) * tanhap(cn);
                Oh[idx] = __float2half(hn);
                if (wf) Of[idx] = hn;
            }
        }
    }
}

// =========================================================================
// ONE merged prologue kernel (packing + init)
// =========================================================================
#define S_W1   (G4H*256)
#define S_W2   (G4H*512)
#define S_B1   (VV*G4H)
#define S_IN   BH
#define S_TOT  (S_W1 + S_W2 + S_B1 + S_IN)

__global__ void prologue(const float* __restrict__ h0,  const float* __restrict__ c0,
                         const float* __restrict__ emb, const float* __restrict__ Wih0,
                         const float* __restrict__ Whh0,const float* __restrict__ Wih1,
                         const float* __restrict__ Whh1)
{
    int idx = blockIdx.x * 256 + threadIdx.x;
    if (idx < S_W1) {
        int m = idx >> 8, k = idx & 255;
        g_W1[idx] = __float2half(Whh0[orig_row(m) * HH + k]);
        return;
    }
    idx -= S_W1;
    if (idx < S_W2) {
        int m = idx >> 9, k = idx & 511;
        int row = orig_row(m);
        g_W2[idx] = __float2half((k < HH) ? Wih1[row * HH + k] : Whh1[row * HH + k - HH]);
        return;
    }
    idx -= S_W2;
    if (idx < S_B1) {
        int v = idx >> 10, m = idx & 1023;
        int row = orig_row(m);
        float s = 0.f;
        #pragma unroll
        for (int d = 0; d < DIN; ++d) s += emb[v * DIN + d] * Wih0[row * DIN + d];
        g_bias1[idx] = s;
        return;
    }
    idx -= S_B1;
    if (idx < S_IN) {
        float a = h0[idx], b = h0[BH + idx];
        g_h1[0][idx] = __float2half(a);  g_h1f[idx] = a;
        g_h2[0][idx] = __float2half(b);  g_h2f[idx] = b;
        g_c1[idx] = c0[idx];
        g_c2[idx] = c0[BH + idx];
    }
}

__global__ void fc_kernel(const float* __restrict__ Wf, const float* __restrict__ bf,
                          float* __restrict__ out)
{
    __shared__ float hs[8][HH];
    const int b0 = blockIdx.x * 8;
    for (int i = threadIdx.x; i < 8 * HH; i += 256)
        hs[i / HH][i % HH] = g_h2f[(b0 + i / HH) * HH + (i % HH)];
    __syncthreads();
    for (int idx = threadIdx.x; idx < 8 * VV; idx += 256) {
        const int bl = idx / VV, v = idx % VV;
        const float* __restrict__ wr = Wf + v * HH;
        const float* __restrict__ hp = hs[bl];
        float s = bf[v];
        #pragma unroll 8
        for (int k = 0; k < HH; k++) s += hp[k] * wr[k];
        out[(b0 + bl) * VV + v] = s;
    }
}
__global__ void finalize(float* __restrict__ out) {
    int i = blockIdx.x * 256 + threadIdx.x;
    if (i < BH) {
        out[OFF_H + i]      = g_h1f[i];
        out[OFF_H + BH + i] = g_h2f[i];
        out[OFF_C + i]      = g_c1[i];
        out[OFF_C + BH + i] = g_c2[i];
    }
}

// =========================================================================
extern "C" void kernel_launch(void* const* d_in, const int* in_sizes, int n_in,
                              void* d_out, int out_size)
{
    const int*   x    = (const int*)  d_in[0];
    const float* h0   = (const float*)d_in[1];
    const float* c0   = (const float*)d_in[2];
    const float* emb  = (const float*)d_in[3];
    const float* Wih0 = (const float*)d_in[4];
    const float* Whh0 = (const float*)d_in[5];
    const float* Wih1 = (const float*)d_in[6];
    const float* Whh1 = (const float*)d_in[7];
    const float* fcW  = (const float*)d_in[8];
    const float* fcb  = (const float*)d_in[9];
    float* out = (float*)d_out;

    cudaFuncSetAttribute(lstm_step, cudaFuncAttributeMaxDynamicSharedMemorySize, SMEM_TOTAL);

    prologue<<<(S_TOT + 255) / 256, 256>>>(h0, c0, emb, Wih0, Whh0, Wih1, Whh1);

    // layer1(0); then fused {layer2(t), layer1(t+1)} for t=0..78; then layer2(79)
    lstm_step<<<dim3(16, 64, 1), 128, SMEM_TOTAL>>>(x, 0, 0, 1);
    for (int t = 0; t < TT - 1; ++t)
        lstm_step<<<dim3(16, 64, 2), 128, SMEM_TOTAL>>>(x, t, t + 1, 0);
    lstm_step<<<dim3(16, 64, 1), 128, SMEM_TOTAL>>>(x, TT - 1, 0, 2);

    fc_kernel<<<BB / 8, 256>>>(fcW, fcb, out);
    finalize <<<(BH + 255) / 256, 256>>>(out);
}

// round 17
// speedup vs baseline: 1.2160x; 1.0234x over previous
#include <cuda_runtime.h>
#include <cuda_fp16.h>
#include <cstdint>

#define BB    4096
#define TT    80
#define HH    256
#define DIN   8
#define VV    80
#define G4H   1024
#define BH    (BB*HH)
#define OFF_H (BB*VV)
#define OFF_C (OFF_H + 2*BH)

// ---------------- device scratch (no allocation allowed) ----------------
__device__ __half g_W1[G4H*256];          // layer1 hh, packed cols, K contig
__device__ __half g_W2[G4H*512];          // layer2 [ih | hh]
__device__ float  g_bias1[VV*G4H];        // (W_ih0 @ emb[v]) packed col order
__device__ __half g_h1[2][BH], g_h2[2][BH];   // fp16 recurrent state (ping-pong)
__device__ float  g_h1f[BH], g_h2f[BH];       // fp32 shadow of FINAL h
__device__ float  g_c1[BH], g_c2[BH];

// packed column m -> original gate row (g*H + j); one thread's HMMA accum cols
// over an n8-tile-pair = gates i,f,g,o of one hidden unit j
__host__ __device__ __forceinline__ int orig_row(int m) {
    int j = 4 * (m >> 4) + ((m >> 1) & 3);
    int g = (m & 1) | (((m >> 3) & 1) << 1);
    return g * HH + j;
}

// ---------------- PTX helpers ----------------
__device__ __forceinline__ uint32_t smem_u32(const void* p) {
    uint32_t a;
    asm("{ .reg .u64 t; cvta.to.shared.u64 t, %1; cvt.u32.u64 %0, t; }" : "=r"(a) : "l"(p));
    return a;
}
__device__ __forceinline__ void cpa16(uint32_t s, const void* g) {
    asm volatile("cp.async.cg.shared.global [%0], [%1], 16;" :: "r"(s), "l"(g));
}
__device__ __forceinline__ void cpa_commit() {
    asm volatile("cp.async.commit_group;" ::: "memory");
}
template<int N>
__device__ __forceinline__ void cpa_wait() {
    asm volatile("cp.async.wait_group %0;" :: "n"(N) : "memory");
}
__device__ __forceinline__ void ldsm4(uint32_t* r, uint32_t addr) {
    asm volatile("ldmatrix.sync.aligned.m8n8.x4.shared.b16 {%0,%1,%2,%3}, [%4];"
                 : "=r"(r[0]), "=r"(r[1]), "=r"(r[2]), "=r"(r[3]) : "r"(addr));
}
__device__ __forceinline__ void mma16816h(float* c, const uint32_t* a, uint32_t b0, uint32_t b1) {
    asm volatile(
        "mma.sync.aligned.m16n8k16.row.col.f32.f16.f16.f32 "
        "{%0,%1,%2,%3}, {%4,%5,%6,%7}, {%8,%9}, {%0,%1,%2,%3};"
        : "+f"(c[0]), "+f"(c[1]), "+f"(c[2]), "+f"(c[3])
        : "r"(a[0]), "r"(a[1]), "r"(a[2]), "r"(a[3]), "r"(b0), "r"(b1));
}

// HW tanh (sm_75+): 1 MUFU op, abs err ~1e-5
__device__ __forceinline__ float tanhap(float x) {
    float y;
    asm("tanh.approx.f32 %0, %1;" : "=f"(y) : "f"(x));
    return y;
}
__device__ __forceinline__ float sigf(float x) {
    return fmaf(0.5f, tanhap(0.5f * x), 0.5f);
}

// SMEM stage: A 8K (64 rows x 128B) | B 16K (128 rows x 128B), SW128, 2 stages
// c-state prefetch (64 rows x 32 fp32, stride 144B) reuses stage 0
#define STG   24576
#define AOFF  0
#define BOFF  8192
#define SMEM_TOTAL (2*STG)
#define CROWB 144

// =========================================================================
// Fused HMMA LSTM step, both layers in one launch.
//   which==1 (layer1 @ t1): K=256 (nc=4), A = h1[p1]
//   which==0 (layer2 @ t2): K=512 (nc=8), A = [h1_cur | h2_prev]
// CTA tile: M=64 x N=128 packed cols (32 hidden units). 4 warps (2M x 2N) of 32x64.
// MMA:LDSM = 2.67 (vs 2.0 at 32x32) -> cuts the L1/smem bandwidth bound.
// Inner schedule = R14-proven granularity: per ks batch af[2]; per np-pair
// batch 2 B-ldsm then 8 MMAs (16 live operand regs; no R11-style spill).
// mode: 0 = z0->layer2(t2), z1->layer1(t1); 1 = layer1 only; 2 = layer2 only
// =========================================================================
__global__ void __launch_bounds__(128, 4) lstm_step(const int* __restrict__ x,
                                                    int t2, int t1, int mode)
{
    extern __shared__ char sm[];
    const uint32_t smb = smem_u32(sm);
    const int tid  = threadIdx.x;
    const int lane = tid & 31, wid = tid >> 5;
    const int wm = wid & 1, wn = wid >> 1;
    const int bx = blockIdx.x;             // 0..7 n-tiles (128 packed cols each)
    const int by = blockIdx.y;             // 0..63 m-tiles (64 rows each)
    const int mbase = by * 64, nb = bx * 128, jbase = bx * 32;

    const int which = (mode == 0) ? (int)blockIdx.z : (mode == 2 ? 0 : 1);

    int nc, KW, tt;
    const __half *W, *A0, *A1;
    __half* Oh;
    float *Of, *cst;
    if (which == 1) {                       // layer 1 at time t1
        const int p = t1 & 1;
        nc = 4; KW = 256; tt = t1;
        W = g_W1;
        A0 = g_h1[p]; A1 = A0;
        Oh = g_h1[p ^ 1]; Of = g_h1f; cst = g_c1;
    } else {                                // layer 2 at time t2
        const int p = t2 & 1;
        nc = 8; KW = 512; tt = t2;
        W = g_W2;
        A0 = g_h1[p ^ 1];                   // h1 at current t2
        A1 = g_h2[p];                       // h2 at t2-1
        Oh = g_h2[p ^ 1]; Of = g_h2f; cst = g_c2;
    }
    const bool wf = (tt == TT - 1);

    // prefetch layer-1 token indices early (latency hides under mainloop)
    const int r = lane >> 2, q = lane & 3;
    int v0 = 0, v1 = 0, v2 = 0, v3 = 0;
    if (which == 1) {
        const int ba = mbase + wm * 32 + r;
        v0 = x[ba * TT + tt];         v1 = x[(ba + 8) * TT + tt];
        v2 = x[(ba + 16) * TT + tt];  v3 = x[(ba + 24) * TT + tt];
    }

    float acc[2][8][4];
    #pragma unroll
    for (int i = 0; i < 2; i++)
        #pragma unroll
        for (int j = 0; j < 8; j++)
            #pragma unroll
            for (int k = 0; k < 4; k++) acc[i][j][k] = 0.f;

    // per-thread cp.async offsets: 128 threads cover 16 rows x 8 chunks per iter
    const int lrow = tid >> 3, lch = tid & 7;
    const uint32_t lso = (uint32_t)((lrow * 128 + lch * 16) ^ ((lrow & 7) << 4));

    auto load_chunk = [&](int c) {
        const uint32_t sb = smb + (c & 1) * STG;
        const __half* ap = (c < 4) ? A0 : A1;
        const int ko = (c & 3) * 64;
        #pragma unroll
        for (int it = 0; it < 4; ++it) {                 // A: 64 rows x 8 16B-chunks
            const int row = lrow + it * 16;
            const uint32_t so = lso + it * 16 * 128;
            cpa16(sb + AOFF + so, ap + (mbase + row) * HH + ko + lch * 8);
        }
        #pragma unroll
        for (int it = 0; it < 8; ++it) {                 // B: 128 rows x 8 chunks
            const int row = lrow + it * 16;
            const uint32_t so = lso + it * 16 * 128;
            cpa16(sb + BOFF + so, W + (nb + row) * KW + c * 64 + lch * 8);
        }
        cpa_commit();
    };

    // c-state prefetch into stage 0 (free during last chunk's compute:
    // last chunk uses stage (nc-1)&1 == 1 for nc=4 and nc=8)
    const int crow = tid >> 3, cch = tid & 7;
    auto load_cstate = [&]() {
        #pragma unroll
        for (int it = 0; it < 4; ++it) {
            const int row = crow + it * 16;
            cpa16(smb + (uint32_t)(row * CROWB + cch * 16),
                  cst + (size_t)(mbase + row) * HH + jbase + cch * 4);
        }
        cpa_commit();
    };

    // --- single-sync 2-stage pipeline: wait; sync; issue next load; compute ---
    load_chunk(0);
    for (int c = 0; c < nc; ++c) {
        cpa_wait<0>();
        __syncthreads();            // separates compute(c-1) readers from load(c+1) writers
        if (c + 1 < nc) load_chunk(c + 1);
        else            load_cstate();

        const uint32_t sb = smb + (c & 1) * STG;
        #pragma unroll
        for (int ks = 0; ks < 4; ++ks) {
            uint32_t af[2][4];
            #pragma unroll
            for (int mt = 0; mt < 2; ++mt) {
                const int row  = wm * 32 + mt * 16 + (lane & 15);
                const uint32_t so = (uint32_t)((row * 128 + ks * 32 + ((lane >> 4) & 1) * 16)
                                               ^ ((row & 7) << 4));
                ldsm4(af[mt], sb + AOFF + so);
            }
            #pragma unroll
            for (int half = 0; half < 2; ++half) {
                uint32_t bf[2][4];
                #pragma unroll
                for (int nq = 0; nq < 2; ++nq) {
                    const int np = half * 2 + nq;
                    const int brow = wn * 64 + np * 16 + (lane & 7) + ((lane >> 4) & 1) * 8;
                    const uint32_t so = (uint32_t)((brow * 128 + ks * 32 + ((lane >> 3) & 1) * 16)
                                                   ^ ((brow & 7) << 4));
                    ldsm4(bf[nq], sb + BOFF + so);
                }
                #pragma unroll
                for (int nq = 0; nq < 2; ++nq) {
                    const int np = half * 2 + nq;
                    #pragma unroll
                    for (int mt = 0; mt < 2; ++mt)
                        #pragma unroll
                        for (int h = 0; h < 2; ++h)
                            mma16816h(acc[mt][2*np + h], af[mt], bf[nq][2*h], bf[nq][2*h + 1]);
                }
            }
        }
    }
    cpa_wait<0>();
    __syncthreads();                // c-state visible to all epilogue readers

    // ---- fused LSTM epilogue: all 4 gates of (b, j) live in this thread ----
    #pragma unroll
    for (int mt = 0; mt < 2; ++mt) {
        const int srow = wm * 32 + mt * 16 + r;
        const int b0 = mbase + srow;
        const int w0 = (mt == 0) ? v0 : v2;
        const int w1 = (mt == 0) ? v1 : v3;
        #pragma unroll
        for (int np = 0; np < 4; ++np) {
            const int jl = wn * 16 + np * 4 + q;
            const int j = jbase + jl;
            float gi0 = acc[mt][2*np][0],   gf0 = acc[mt][2*np][1];
            float gi1 = acc[mt][2*np][2],   gf1 = acc[mt][2*np][3];
            float gg0 = acc[mt][2*np+1][0], go0 = acc[mt][2*np+1][1];
            float gg1 = acc[mt][2*np+1][2], go1 = acc[mt][2*np+1][3];
            if (which == 1) {
                const int m0 = bx * 128 + wn * 64 + np * 16 + 2 * q;
                float2 u;
                u = *(const float2*)(g_bias1 + w0 * G4H + m0);     gi0 += u.x; gf0 += u.y;
                u = *(const float2*)(g_bias1 + w0 * G4H + m0 + 8); gg0 += u.x; go0 += u.y;
                u = *(const float2*)(g_bias1 + w1 * G4H + m0);     gi1 += u.x; gf1 += u.y;
                u = *(const float2*)(g_bias1 + w1 * G4H + m0 + 8); gg1 += u.x; go1 += u.y;
            }
            {
                const int idx = b0 * HH + j;
                float co = *(const float*)(sm + srow * CROWB + jl * 4);
                float cn = sigf(gf0) * co + sigf(gi0) * tanhap(gg0);
                cst[idx] = cn;
                float hn = sigf(go0) * tanhap(cn);
                Oh[idx] = __float2half(hn);
                if (wf) Of[idx] = hn;
            }
            {
                const int idx = (b0 + 8) * HH + j;
                float co = *(const float*)(sm + (srow + 8) * CROWB + jl * 4);
                float cn = sigf(gf1) * co + sigf(gi1) * tanhap(gg1);
                cst[idx] = cn;
                float hn = sigf(go1) * tanhap(cn);
                Oh[idx] = __float2half(hn);
                if (wf) Of[idx] = hn;
            }
        }
    }
}

// =========================================================================
// ONE merged prologue kernel (packing + init)
// =========================================================================
#define S_W1   (G4H*256)
#define S_W2   (G4H*512)
#define S_B1   (VV*G4H)
#define S_IN   BH
#define S_TOT  (S_W1 + S_W2 + S_B1 + S_IN)

__global__ void prologue(const float* __restrict__ h0,  const float* __restrict__ c0,
                         const float* __restrict__ emb, const float* __restrict__ Wih0,
                         const float* __restrict__ Whh0,const float* __restrict__ Wih1,
                         const float* __restrict__ Whh1)
{
    int idx = blockIdx.x * 256 + threadIdx.x;
    if (idx < S_W1) {
        int m = idx >> 8, k = idx & 255;
        g_W1[idx] = __float2half(Whh0[orig_row(m) * HH + k]);
        return;
    }
    idx -= S_W1;
    if (idx < S_W2) {
        int m = idx >> 9, k = idx & 511;
        int row = orig_row(m);
        g_W2[idx] = __float2half((k < HH) ? Wih1[row * HH + k] : Whh1[row * HH + k - HH]);
        return;
    }
    idx -= S_W2;
    if (idx < S_B1) {
        int v = idx >> 10, m = idx & 1023;
        int row = orig_row(m);
        float s = 0.f;
        #pragma unroll
        for (int d = 0; d < DIN; ++d) s += emb[v * DIN + d] * Wih0[row * DIN + d];
        g_bias1[idx] = s;
        return;
    }
    idx -= S_B1;
    if (idx < S_IN) {
        float a = h0[idx], b = h0[BH + idx];
        g_h1[0][idx] = __float2half(a);  g_h1f[idx] = a;
        g_h2[0][idx] = __float2half(b);  g_h2f[idx] = b;
        g_c1[idx] = c0[idx];
        g_c2[idx] = c0[BH + idx];
    }
}

__global__ void fc_kernel(const float* __restrict__ Wf, const float* __restrict__ bf,
                          float* __restrict__ out)
{
    __shared__ float hs[8][HH];
    const int b0 = blockIdx.x * 8;
    for (int i = threadIdx.x; i < 8 * HH; i += 256)
        hs[i / HH][i % HH] = g_h2f[(b0 + i / HH) * HH + (i % HH)];
    __syncthreads();
    for (int idx = threadIdx.x; idx < 8 * VV; idx += 256) {
        const int bl = idx / VV, v = idx % VV;
        const float* __restrict__ wr = Wf + v * HH;
        const float* __restrict__ hp = hs[bl];
        float s = bf[v];
        #pragma unroll 8
        for (int k = 0; k < HH; k++) s += hp[k] * wr[k];
        out[(b0 + bl) * VV + v] = s;
    }
}
__global__ void finalize(float* __restrict__ out) {
    int i = blockIdx.x * 256 + threadIdx.x;
    if (i < BH) {
        out[OFF_H + i]      = g_h1f[i];
        out[OFF_H + BH + i] = g_h2f[i];
        out[OFF_C + i]      = g_c1[i];
        out[OFF_C + BH + i] = g_c2[i];
    }
}

// =========================================================================
extern "C" void kernel_launch(void* const* d_in, const int* in_sizes, int n_in,
                              void* d_out, int out_size)
{
    const int*   x    = (const int*)  d_in[0];
    const float* h0   = (const float*)d_in[1];
    const float* c0   = (const float*)d_in[2];
    const float* emb  = (const float*)d_in[3];
    const float* Wih0 = (const float*)d_in[4];
    const float* Whh0 = (const float*)d_in[5];
    const float* Wih1 = (const float*)d_in[6];
    const float* Whh1 = (const float*)d_in[7];
    const float* fcW  = (const float*)d_in[8];
    const float* fcb  = (const float*)d_in[9];
    float* out = (float*)d_out;

    cudaFuncSetAttribute(lstm_step, cudaFuncAttributeMaxDynamicSharedMemorySize, SMEM_TOTAL);

    prologue<<<(S_TOT + 255) / 256, 256>>>(h0, c0, emb, Wih0, Whh0, Wih1, Whh1);

    // layer1(0); then fused {layer2(t), layer1(t+1)} for t=0..78; then layer2(79)
    lstm_step<<<dim3(8, 64, 1), 128, SMEM_TOTAL>>>(x, 0, 0, 1);
    for (int t = 0; t < TT - 1; ++t)
        lstm_step<<<dim3(8, 64, 2), 128, SMEM_TOTAL>>>(x, t, t + 1, 0);
    lstm_step<<<dim3(8, 64, 1), 128, SMEM_TOTAL>>>(x, TT - 1, 0, 2);

    fc_kernel<<<BB / 8, 256>>>(fcW, fcb, out);
    finalize <<<(BH + 255) / 256, 256>>>(out);
}